// round 4
// baseline (speedup 1.0000x reference)
#include <cuda_runtime.h>

// TaylorActivation: out = Horner(x; c[0..8]), elementwise over 512x65536 fp32.
// HBM-bound stream: 128 MiB in + 128 MiB out. Floor = 32us @ 8TB/s.
//
// R2: coefficients in __constant__ (filled by capturable D2D memcpy node),
//     4x float4 per thread with front-batched loads (MLP_p1=4).

__constant__ float c_w[9];

__global__ void __launch_bounds__(256)
taylor_kernel(const float4* __restrict__ x,
              float4* __restrict__ out,
              int n4)
{
    // Each block covers 256 threads * 4 float4 = 1024 float4, contiguous,
    // coalesced per-warp at stride blockDim.
    int base = blockIdx.x * (256 * 4) + threadIdx.x;

    // Front-batched independent loads (MLP_p1 = 4).
    float4 v0 = x[base + 0 * 256];
    float4 v1 = x[base + 1 * 256];
    float4 v2 = x[base + 2 * 256];
    float4 v3 = x[base + 3 * 256];

    const float c0 = c_w[0], c1 = c_w[1], c2 = c_w[2], c3 = c_w[3],
                c4 = c_w[4], c5 = c_w[5], c6 = c_w[6], c7 = c_w[7],
                c8 = c_w[8];

    float4 r0, r1, r2, r3;
    r0.x = r0.y = r0.z = r0.w = c8;
    r1.x = r1.y = r1.z = r1.w = c8;
    r2.x = r2.y = r2.z = r2.w = c8;
    r3.x = r3.y = r3.z = r3.w = c8;

#define STEP(ck)                                                             \
    r0.x = fmaf(r0.x, v0.x, ck); r0.y = fmaf(r0.y, v0.y, ck);                \
    r0.z = fmaf(r0.z, v0.z, ck); r0.w = fmaf(r0.w, v0.w, ck);                \
    r1.x = fmaf(r1.x, v1.x, ck); r1.y = fmaf(r1.y, v1.y, ck);                \
    r1.z = fmaf(r1.z, v1.z, ck); r1.w = fmaf(r1.w, v1.w, ck);                \
    r2.x = fmaf(r2.x, v2.x, ck); r2.y = fmaf(r2.y, v2.y, ck);                \
    r2.z = fmaf(r2.z, v2.z, ck); r2.w = fmaf(r2.w, v2.w, ck);                \
    r3.x = fmaf(r3.x, v3.x, ck); r3.y = fmaf(r3.y, v3.y, ck);                \
    r3.z = fmaf(r3.z, v3.z, ck); r3.w = fmaf(r3.w, v3.w, ck);

    STEP(c7) STEP(c6) STEP(c5) STEP(c4)
    STEP(c3) STEP(c2) STEP(c1) STEP(c0)
#undef STEP

    out[base + 0 * 256] = r0;
    out[base + 1 * 256] = r1;
    out[base + 2 * 256] = r2;
    out[base + 3 * 256] = r3;
}

extern "C" void kernel_launch(void* const* d_in, const int* in_sizes, int n_in,
                              void* d_out, int out_size)
{
    const float* x = (const float*)d_in[0];   // (512, 65536) fp32
    const float* w = (const float*)d_in[1];   // (9, 1) fp32
    float* out = (float*)d_out;

    // Capturable memcpy node: device buffer -> __constant__ bank.
    cudaMemcpyToSymbolAsync(c_w, w, 9 * sizeof(float), 0,
                            cudaMemcpyDeviceToDevice, 0);

    int n = in_sizes[0];          // 33554432
    int n4 = n / 4;               // 8388608 float4
    int blocks = n4 / (256 * 4);  // 8192 (exact: 8388608 / 1024)

    taylor_kernel<<<blocks, 256>>>(
        (const float4*)x, (float4*)out, n4);
}

// round 7
// speedup vs baseline: 1.0309x; 1.0309x over previous
#include <cuda_runtime.h>

// TaylorActivation: out = Horner(x; c[0..8]), elementwise over 512x65536 fp32.
// HBM-bound stream: 128 MiB in + 128 MiB out. Floor = 32us @ 8TB/s.
//
// R4: single kernel node (no memcpy in graph — it cost ~5.5us/replay).
//     Coefficients read in-kernel via 3 vectorized broadcast LDGs.
//     4x float4 per thread, front-batched (MLP_p1=4), streaming cache hints.

__global__ void __launch_bounds__(256)
taylor_kernel(const float4* __restrict__ x,
              const float* __restrict__ w,
              float4* __restrict__ out)
{
    int base = blockIdx.x * (256 * 4) + threadIdx.x;

    // Front-batched independent streaming loads (MLP_p1 = 4).
    float4 v0 = __ldcs(&x[base + 0 * 256]);
    float4 v1 = __ldcs(&x[base + 1 * 256]);
    float4 v2 = __ldcs(&x[base + 2 * 256]);
    float4 v3 = __ldcs(&x[base + 3 * 256]);

    // 9 coefficients via 3 loads (broadcast, L1-resident after first warp).
    const float4 wa = __ldg((const float4*)&w[0]);  // c0..c3
    const float4 wb = __ldg((const float4*)&w[4]);  // c4..c7
    const float  c8 = __ldg(&w[8]);
    const float c0 = wa.x, c1 = wa.y, c2 = wa.z, c3 = wa.w;
    const float c4 = wb.x, c5 = wb.y, c6 = wb.z, c7 = wb.w;

    float4 r0, r1, r2, r3;
    r0.x = r0.y = r0.z = r0.w = c8;
    r1.x = r1.y = r1.z = r1.w = c8;
    r2.x = r2.y = r2.z = r2.w = c8;
    r3.x = r3.y = r3.z = r3.w = c8;

#define STEP(ck)                                                             \
    r0.x = fmaf(r0.x, v0.x, ck); r0.y = fmaf(r0.y, v0.y, ck);                \
    r0.z = fmaf(r0.z, v0.z, ck); r0.w = fmaf(r0.w, v0.w, ck);                \
    r1.x = fmaf(r1.x, v1.x, ck); r1.y = fmaf(r1.y, v1.y, ck);                \
    r1.z = fmaf(r1.z, v1.z, ck); r1.w = fmaf(r1.w, v1.w, ck);                \
    r2.x = fmaf(r2.x, v2.x, ck); r2.y = fmaf(r2.y, v2.y, ck);                \
    r2.z = fmaf(r2.z, v2.z, ck); r2.w = fmaf(r2.w, v2.w, ck);                \
    r3.x = fmaf(r3.x, v3.x, ck); r3.y = fmaf(r3.y, v3.y, ck);                \
    r3.z = fmaf(r3.z, v3.z, ck); r3.w = fmaf(r3.w, v3.w, ck);

    STEP(c7) STEP(c6) STEP(c5) STEP(c4)
    STEP(c3) STEP(c2) STEP(c1) STEP(c0)
#undef STEP

    __stcs(&out[base + 0 * 256], r0);
    __stcs(&out[base + 1 * 256], r1);
    __stcs(&out[base + 2 * 256], r2);
    __stcs(&out[base + 3 * 256], r3);
}

extern "C" void kernel_launch(void* const* d_in, const int* in_sizes, int n_in,
                              void* d_out, int out_size)
{
    const float* x = (const float*)d_in[0];   // (512, 65536) fp32
    const float* w = (const float*)d_in[1];   // (9, 1) fp32
    float* out = (float*)d_out;

    int n = in_sizes[0];          // 33554432
    int n4 = n / 4;               // 8388608 float4
    int blocks = n4 / (256 * 4);  // 8192 (exact)

    taylor_kernel<<<blocks, 256>>>(
        (const float4*)x, w, (float4*)out);
}